// round 1
// baseline (speedup 1.0000x reference)
#include <cuda_runtime.h>

// PGJANET recurrent scan: B=256, T=2048, H=64, O=2.
// Persistent kernel: 128 blocks x 256 threads, each block owns 2 batch elements
// for the whole sequence. Weights live in registers (112 floats/thread),
// h/u state lives in shared memory, x is preloaded to shared memory.

#define TB   2048
#define BATCH 256
#define HID  64

__device__ __forceinline__ float sigmoidf_(float v) {
    return 1.0f / (1.0f + __expf(-v));
}

__global__ void __launch_bounds__(256, 1)
pgjanet_kernel(const float* __restrict__ x,
               const float* __restrict__ h0,
               const float* __restrict__ Wa,  const float* __restrict__ ba,
               const float* __restrict__ Wp1, const float* __restrict__ bp1,
               const float* __restrict__ Wp2, const float* __restrict__ bp2,
               const float* __restrict__ Wf,  const float* __restrict__ bf,
               const float* __restrict__ Wg,  const float* __restrict__ bg,
               const float* __restrict__ Wo,  const float* __restrict__ bo,
               float* __restrict__ out)
{
    __shared__ __align__(16) float xbuf[2][2 * TB];     // 32 KB: x for both batch elems
    __shared__ __align__(16) float hu[2][128];          // [b][0:64)=h, [64:128)=u
    __shared__ __align__(16) float part[2][3][4][64];   // partial dot sums
    __shared__ float scal[2][4];                        // amp, cos, sin per b
    __shared__ float ypart[4][2];                       // per-warp y partials

    const int tid = threadIdx.x;
    const int j   = tid & 63;     // hidden unit
    const int s   = tid >> 6;     // k-slice 0..3
    const int b0  = blockIdx.x * 2;

    // ---- weight slices in registers ----
    float wa[16], wp1[16], wp2[16], wf[32], wg[32];
    {
        const float* Wa_r  = Wa  + j * 65 + s * 16;
        const float* Wp1_r = Wp1 + j * 65 + s * 16;
        const float* Wp2_r = Wp2 + j * 65 + s * 16;
        #pragma unroll
        for (int i = 0; i < 16; i++) {
            wa[i] = Wa_r[i]; wp1[i] = Wp1_r[i]; wp2[i] = Wp2_r[i];
        }
        const float* Wf_r = Wf + j * 128 + s * 32;
        const float* Wg_r = Wg + j * 128 + s * 32;
        #pragma unroll
        for (int i = 0; i < 32; i++) {
            wf[i] = Wf_r[i]; wg[i] = Wg_r[i];
        }
    }

    // ---- finalize constants (threads 0..127: (j, b) finalize owners) ----
    float walast = 0.f, ba_r = 0.f, w1last = 0.f, b1_r = 0.f;
    float w2last = 0.f, b2_r = 0.f, bf_r = 0.f, bg_r = 0.f;
    float wo0 = 0.f, wo1 = 0.f;
    if (tid < 128) {
        walast = Wa[j * 65 + 64];  ba_r = ba[j];
        w1last = Wp1[j * 65 + 64]; b1_r = bp1[j];
        w2last = Wp2[j * 65 + 64]; b2_r = bp2[j];
        bf_r = bf[j]; bg_r = bg[j];
        wo0 = Wo[j]; wo1 = Wo[64 + j];
    }
    const float bo_r = (tid < 4) ? bo[tid & 1] : 0.f;

    // ---- preload x for both batch elems into smem ----
    #pragma unroll
    for (int b = 0; b < 2; b++) {
        const float4* src = (const float4*)(x + (size_t)(b0 + b) * TB * 2);
        float4* dst = (float4*)xbuf[b];
        for (int i = tid; i < TB * 2 / 4; i += 256) dst[i] = src[i];
    }
    if (tid < 128) {
        int b = tid >> 6;
        hu[b][j] = h0[(size_t)(b0 + b) * HID + j];
    }
    __syncthreads();

    for (int t = 0; t < TB; t++) {
        // per-step scalar inputs: amp = |z|, cos = i/amp, sin = q/amp
        if (tid < 2) {
            float iv = xbuf[tid][2 * t];
            float qv = xbuf[tid][2 * t + 1];
            float amp = sqrtf(fmaf(iv, iv, qv * qv));
            float inv = (amp > 0.f) ? (1.f / amp) : 0.f;
            scal[tid][0] = amp;
            scal[tid][1] = (amp > 0.f) ? iv * inv : 1.f;
            scal[tid][2] = qv * inv;
        }

        // ---- phase 1: partial dots for a / p1 / p2 (k-slice s) ----
        #pragma unroll
        for (int b = 0; b < 2; b++) {
            const float4* hp = (const float4*)&hu[b][s * 16];
            float aa = 0.f, a1 = 0.f, a2 = 0.f;
            #pragma unroll
            for (int r = 0; r < 4; r++) {
                float4 h4 = hp[r];
                aa = fmaf(wa [4*r+0], h4.x, aa); a1 = fmaf(wp1[4*r+0], h4.x, a1); a2 = fmaf(wp2[4*r+0], h4.x, a2);
                aa = fmaf(wa [4*r+1], h4.y, aa); a1 = fmaf(wp1[4*r+1], h4.y, a1); a2 = fmaf(wp2[4*r+1], h4.y, a2);
                aa = fmaf(wa [4*r+2], h4.z, aa); a1 = fmaf(wp1[4*r+2], h4.z, a1); a2 = fmaf(wp2[4*r+2], h4.z, a2);
                aa = fmaf(wa [4*r+3], h4.w, aa); a1 = fmaf(wp1[4*r+3], h4.w, a1); a2 = fmaf(wp2[4*r+3], h4.w, a2);
            }
            part[b][0][s][j] = aa;
            part[b][1][s][j] = a1;
            part[b][2][s][j] = a2;
        }
        __syncthreads();

        // ---- finalize u (threads 0..127, one per (j, b)) ----
        if (tid < 128) {
            int b = tid >> 6;
            float sa = part[b][0][0][j] + part[b][0][1][j] + part[b][0][2][j] + part[b][0][3][j];
            float s1 = part[b][1][0][j] + part[b][1][1][j] + part[b][1][2][j] + part[b][1][3][j];
            float s2 = part[b][2][0][j] + part[b][2][1][j] + part[b][2][2][j] + part[b][2][3][j];
            float a  = tanhf(fmaf(scal[b][0], walast, sa) + ba_r);
            float p1 = tanhf(fmaf(scal[b][1], w1last, s1) + b1_r);
            float p2 = tanhf(fmaf(scal[b][2], w2last, s2) + b2_r);
            float u = a * p1 * p2 * (1.f - a) * (1.f - p1) * (1.f - p2);
            hu[b][64 + j] = u;
        }
        __syncthreads();

        // ---- phase 2: partial dots for f / g over hu (k-slice s of 128) ----
        #pragma unroll
        for (int b = 0; b < 2; b++) {
            const float4* hup = (const float4*)&hu[b][s * 32];
            float af = 0.f, ag = 0.f;
            #pragma unroll
            for (int r = 0; r < 8; r++) {
                float4 v = hup[r];
                af = fmaf(wf[4*r+0], v.x, af); ag = fmaf(wg[4*r+0], v.x, ag);
                af = fmaf(wf[4*r+1], v.y, af); ag = fmaf(wg[4*r+1], v.y, ag);
                af = fmaf(wf[4*r+2], v.z, af); ag = fmaf(wg[4*r+2], v.z, ag);
                af = fmaf(wf[4*r+3], v.w, af); ag = fmaf(wg[4*r+3], v.w, ag);
            }
            part[b][0][s][j] = af;
            part[b][1][s][j] = ag;
        }
        __syncthreads();

        // ---- finalize h + per-warp y reduction ----
        if (tid < 128) {
            int b = tid >> 6;
            float sf = part[b][0][0][j] + part[b][0][1][j] + part[b][0][2][j] + part[b][0][3][j];
            float sg = part[b][1][0][j] + part[b][1][1][j] + part[b][1][2][j] + part[b][1][3][j];
            float f = sigmoidf_(sf + bf_r);
            float g = tanhf(sg + bg_r);
            float hold = hu[b][j];
            float hn = fmaf(f, hold - g, g);   // f*h + (1-f)*g
            hu[b][j] = hn;

            float t0 = hn * wo0;
            float t1 = hn * wo1;
            #pragma unroll
            for (int off = 16; off > 0; off >>= 1) {
                t0 += __shfl_xor_sync(0xffffffffu, t0, off);
                t1 += __shfl_xor_sync(0xffffffffu, t1, off);
            }
            if ((tid & 31) == 0) {
                ypart[tid >> 5][0] = t0;
                ypart[tid >> 5][1] = t1;
            }
        }
        __syncthreads();

        if (tid < 4) {
            int o = tid & 1, bb = tid >> 1;
            out[((size_t)(b0 + bb) * TB + t) * 2 + o] =
                ypart[bb * 2][o] + ypart[bb * 2 + 1][o] + bo_r;
        }
    }
}

extern "C" void kernel_launch(void* const* d_in, const int* in_sizes, int n_in,
                              void* d_out, int out_size)
{
    const float* x   = (const float*)d_in[0];
    const float* h0  = (const float*)d_in[1];
    const float* Wa  = (const float*)d_in[2];
    const float* ba  = (const float*)d_in[3];
    const float* Wp1 = (const float*)d_in[4];
    const float* bp1 = (const float*)d_in[5];
    const float* Wp2 = (const float*)d_in[6];
    const float* bp2 = (const float*)d_in[7];
    const float* Wf  = (const float*)d_in[8];
    const float* bf  = (const float*)d_in[9];
    const float* Wg  = (const float*)d_in[10];
    const float* bg  = (const float*)d_in[11];
    const float* Wo  = (const float*)d_in[12];
    const float* bo  = (const float*)d_in[13];
    float* out = (float*)d_out;

    pgjanet_kernel<<<BATCH / 2, 256>>>(x, h0, Wa, ba, Wp1, bp1, Wp2, bp2,
                                       Wf, bf, Wg, bg, Wo, bo, out);
}